// round 4
// baseline (speedup 1.0000x reference)
#include <cuda_runtime.h>
#include <cuda_bf16.h>

// ---------------------------------------------------------------------------
// PointGenerator: X_world = (E_ @ n2r @ K_^-1) @ [x*d, y*d, d, 1]
//
// Per-camera matrix M (3x4), derived analytically:
//   M[i][0] =  E[i][0]/f
//   M[i][1] = -E[i][1]/f
//   M[i][2] = (-E[i][0]*cx + E[i][1]*cy)/f - E[i][2]
//   M[i][3] =  E[i][3]
// Output row 3 is identically [0,0,0,1] -> w = 1.
// image_coords[y,x]-0.5 == (float)y,(float)x exactly.
//
// Single persistent kernel: each block builds all camera matrices in smem,
// then grid-stride loops over 4-point quads with software-pipelined loads.
// ---------------------------------------------------------------------------

#define MAX_CAMS   256
#define NTHREADS   256
#define BLKS_PER_SM 5
#define NSM        148

__global__ void __launch_bounds__(NTHREADS, BLKS_PER_SM)
point_gen_kernel(const int*   __restrict__ pidx,     // [N,3] int32
                 const float* __restrict__ depth,    // [N] f32
                 const float* __restrict__ c2w,      // [C,3,4] f32
                 const float* __restrict__ intr,     // [C,3,3] f32
                 float*       __restrict__ out,      // [N,4] f32
                 int npoints, int num_cams) {
    __shared__ float4 s_cam[MAX_CAMS * 3];

    // --- build per-camera matrices directly in smem (tiny, L2-resident) ---
    for (int c = threadIdx.x; c < num_cams; c += NTHREADS) {
        const float* E = c2w + c * 12;
        const float* K = intr + c * 9;
        double f    = (double)K[0];
        double cx   = (double)K[2];
        double cy   = (double)K[5];
        double invf = 1.0 / f;
#pragma unroll
        for (int i = 0; i < 3; i++) {
            double e0 = (double)E[i * 4 + 0];
            double e1 = (double)E[i * 4 + 1];
            double e2 = (double)E[i * 4 + 2];
            double e3 = (double)E[i * 4 + 3];
            float4 r;
            r.x = (float)(e0 * invf);
            r.y = (float)(-e1 * invf);
            r.z = (float)((-e0 * cx + e1 * cy) * invf - e2);
            r.w = (float)e3;
            s_cam[c * 3 + i] = r;
        }
    }
    __syncthreads();

    const int4*   pidx4  = (const int4*)pidx;
    const float4* depth4 = (const float4*)depth;
    float4*       out4   = (float4*)out;

    const int nquads = npoints >> 2;
    const int stride = gridDim.x * NTHREADS;

    int t = blockIdx.x * NTHREADS + threadIdx.x;

    // --- software-pipelined grid-stride loop over quads ---
    int4   a, b, cc;
    float4 d4;
    bool valid = (t < nquads);
    if (valid) {
        a  = pidx4[3 * t + 0];
        b  = pidx4[3 * t + 1];
        cc = pidx4[3 * t + 2];
        d4 = depth4[t];
    }

    while (valid) {
        // prefetch next iteration's globals (in flight during compute below)
        int  tn = t + stride;
        bool vn = (tn < nquads);
        int4   a2, b2, c2;
        float4 d2;
        if (vn) {
            a2 = pidx4[3 * tn + 0];
            b2 = pidx4[3 * tn + 1];
            c2 = pidx4[3 * tn + 2];
            d2 = depth4[tn];
        }

        // current quad: 4 points packed in (a,b,cc), depths in d4
        int   cs[4] = {a.x, a.w, b.z, cc.y};
        int   ys[4] = {a.y, b.x, b.w, cc.z};
        int   xs[4] = {a.z, b.y, cc.x, cc.w};
        float ds[4] = {d4.x, d4.y, d4.z, d4.w};

#pragma unroll
        for (int j = 0; j < 4; j++) {
            float dd = ds[j];
            float xd = (float)xs[j] * dd;
            float yd = (float)ys[j] * dd;
            const float4* M = &s_cam[cs[j] * 3];
            float4 r0 = M[0];
            float4 r1 = M[1];
            float4 r2 = M[2];
            float4 o;
            o.x = fmaf(r0.x, xd, fmaf(r0.y, yd, fmaf(r0.z, dd, r0.w)));
            o.y = fmaf(r1.x, xd, fmaf(r1.y, yd, fmaf(r1.z, dd, r1.w)));
            o.z = fmaf(r2.x, xd, fmaf(r2.y, yd, fmaf(r2.z, dd, r2.w)));
            o.w = 1.0f;
            out4[4 * t + j] = o;
        }

        t = tn; valid = vn;
        a = a2; b = b2; cc = c2; d4 = d2;
    }

    // --- scalar tail (npoints % 4 != 0; not hit for N=2M but kept safe) ---
    int rem = npoints - (nquads << 2);
    int g = blockIdx.x * NTHREADS + threadIdx.x;
    if (g < rem) {
        int p = (nquads << 2) + g;
        int c = pidx[3 * p + 0];
        int y = pidx[3 * p + 1];
        int x = pidx[3 * p + 2];
        float dd = depth[p];
        float xd = (float)x * dd;
        float yd = (float)y * dd;
        float4 r0 = s_cam[c * 3 + 0];
        float4 r1 = s_cam[c * 3 + 1];
        float4 r2 = s_cam[c * 3 + 2];
        float4 o;
        o.x = fmaf(r0.x, xd, fmaf(r0.y, yd, fmaf(r0.z, dd, r0.w)));
        o.y = fmaf(r1.x, xd, fmaf(r1.y, yd, fmaf(r1.z, dd, r1.w)));
        o.z = fmaf(r2.x, xd, fmaf(r2.y, yd, fmaf(r2.z, dd, r2.w)));
        o.w = 1.0f;
        out4[p] = o;
    }
}

extern "C" void kernel_launch(void* const* d_in, const int* in_sizes, int n_in,
                              void* d_out, int out_size) {
    // metadata order: point_indices[N,3] i32, depth[N,1] f32, image_coords (unused),
    //                 camera_to_worlds[C,3,4] f32, intrinsics[C,3,3] f32
    const int*   pidx  = (const int*)d_in[0];
    const float* depth = (const float*)d_in[1];
    const float* c2w   = (const float*)d_in[3];
    const float* intr  = (const float*)d_in[4];
    float*       out   = (float*)d_out;

    int npoints  = in_sizes[0] / 3;
    int num_cams = in_sizes[3] / 12;
    if (num_cams > MAX_CAMS) num_cams = MAX_CAMS;

    int blocks = NSM * BLKS_PER_SM;  // one resident wave, grid-stride covers all
    point_gen_kernel<<<blocks, NTHREADS>>>(pidx, depth, c2w, intr, out,
                                           npoints, num_cams);
}

// round 5
// speedup vs baseline: 1.3174x; 1.3174x over previous
#include <cuda_runtime.h>
#include <cuda_bf16.h>
#include <cstdint>

// ---------------------------------------------------------------------------
// PointGenerator: X_world = (E_ @ n2r @ K_^-1) @ [x*d, y*d, d, 1]
//
// Per-camera matrix M (3x4), fp32:
//   r0 =  E[0,:3]/f ;  r1 = -E[1,:3]/f (col1 negated per row, see below)
//   M[i] = { e_i0/f, -e_i1/f, -M[i].x*cx - M[i].y*cy - e_i2, e_i3 }
// Output w-component identically 1.
//
// R4: TMA-tiled. STG.128 issue cost (12 cyc) made per-thread stores the
// bottleneck (~40K cyc == measured runtime). Replace all global LDG/STG on
// the hot path with cp.async.bulk (1 instruction per 12-16KB tile).
// ---------------------------------------------------------------------------

#define MAX_CAMS 256
#define NTHREADS 256
#define TILE     1024   // points per block

__device__ __forceinline__ uint32_t smem_u32(const void* p) {
    uint32_t a;
    asm("{ .reg .u64 t; cvta.to.shared.u64 t, %1; cvt.u32.u64 %0, t; }"
        : "=r"(a) : "l"(p));
    return a;
}

__device__ __forceinline__ void mbar_init(uint32_t mbar, uint32_t cnt) {
    asm volatile("mbarrier.init.shared.b64 [%0], %1;" :: "r"(mbar), "r"(cnt) : "memory");
}
__device__ __forceinline__ void mbar_expect_tx(uint32_t mbar, uint32_t bytes) {
    asm volatile("mbarrier.arrive.expect_tx.shared.b64 _, [%0], %1;"
                 :: "r"(mbar), "r"(bytes) : "memory");
}
__device__ __forceinline__ void mbar_wait(uint32_t mbar, uint32_t parity) {
    uint32_t done;
    asm volatile(
        "{ .reg .pred p;\n"
        "  mbarrier.try_wait.parity.acquire.cta.shared::cta.b64 p, [%1], %2;\n"
        "  selp.b32 %0, 1, 0, p; }"
        : "=r"(done) : "r"(mbar), "r"(parity) : "memory");
    if (!done) {
        asm volatile(
            "{ .reg .pred P1;\n"
            "WAIT_%=:\n"
            "  mbarrier.try_wait.parity.acquire.cta.shared::cta.b64 P1, [%0], %1, 0x989680;\n"
            "  @P1 bra.uni DONE_%=;\n"
            "  bra.uni WAIT_%=;\n"
            "DONE_%=: }"
            :: "r"(mbar), "r"(parity) : "memory");
    }
}
__device__ __forceinline__ void bulk_load_g2s(uint32_t smem_dst, const void* gmem_src,
                                              uint32_t bytes, uint32_t mbar) {
    asm volatile(
        "cp.async.bulk.shared::cta.global.mbarrier::complete_tx::bytes [%0], [%1], %2, [%3];"
        :: "r"(smem_dst), "l"(gmem_src), "r"(bytes), "r"(mbar) : "memory");
}
__device__ __forceinline__ void bulk_store_s2g(void* gmem_dst, uint32_t smem_src,
                                               uint32_t bytes) {
    asm volatile(
        "cp.async.bulk.global.shared::cta.bulk_group [%0], [%1], %2;"
        :: "l"(gmem_dst), "r"(smem_src), "r"(bytes) : "memory");
}

__global__ void __launch_bounds__(NTHREADS)
point_gen_kernel(const int*   __restrict__ pidx,   // [N,3] i32
                 const float* __restrict__ depth,  // [N]   f32
                 const float* __restrict__ c2w,    // [C,3,4] f32
                 const float* __restrict__ intr,   // [C,3,3] f32
                 float*       __restrict__ out,    // [N,4] f32
                 int npoints, int num_cams) {
    __shared__ float4 s_cam[MAX_CAMS * 3];           // 12 KB
    __shared__ int    s_pidx[TILE * 3];              // 12 KB
    __shared__ float  s_depth[TILE];                 //  4 KB
    __shared__ float4 s_out[TILE];                   // 16 KB
    __shared__ alignas(8) unsigned long long s_mbar;

    const int tid  = threadIdx.x;
    const int base = blockIdx.x * TILE;
    int tile_pts   = npoints - base;
    if (tile_pts > TILE) tile_pts = TILE;
    const int bulk_pts = tile_pts & ~3;  // multiple of 4 -> all bulk sizes %16==0

    const uint32_t mbar    = smem_u32(&s_mbar);
    const uint32_t sp_addr = smem_u32(s_pidx);
    const uint32_t sd_addr = smem_u32(s_depth);
    const uint32_t so_addr = smem_u32(s_out);

    if (tid == 0) mbar_init(mbar, 1);
    __syncthreads();

    // Kick off input TMA first; camera build overlaps it.
    if (tid == 0 && bulk_pts > 0) {
        uint32_t b_pidx  = (uint32_t)bulk_pts * 12u;
        uint32_t b_depth = (uint32_t)bulk_pts * 4u;
        mbar_expect_tx(mbar, b_pidx + b_depth);
        bulk_load_g2s(sp_addr, pidx + (size_t)base * 3, b_pidx, mbar);
        bulk_load_g2s(sd_addr, depth + base, b_depth, mbar);
    }

    // Build per-camera matrices in fp32 (all inputs L2-resident, tiny).
    for (int c = tid; c < num_cams; c += NTHREADS) {
        const float* E = c2w + c * 12;
        const float* K = intr + c * 9;
        float invf = 1.0f / K[0];
        float cx = K[2], cy = K[5];
#pragma unroll
        for (int i = 0; i < 3; i++) {
            float e0 = E[i * 4 + 0];
            float e1 = E[i * 4 + 1];
            float e2 = E[i * 4 + 2];
            float e3 = E[i * 4 + 3];
            float4 r;
            r.x = e0 * invf;
            r.y = -e1 * invf;
            r.z = fmaf(-r.x, cx, fmaf(-r.y, cy, -e2));
            r.w = e3;
            s_cam[c * 3 + i] = r;
        }
    }
    __syncthreads();               // cameras visible to all
    if (bulk_pts > 0) mbar_wait(mbar, 0);

    // Compute: thread handles points tid, tid+256, tid+512, tid+768.
    // Scalar LDS stride-3 per lane -> gcd(3,32)=1 -> conflict-free.
#pragma unroll
    for (int j = 0; j < 4; j++) {
        int p = tid + j * NTHREADS;
        if (p < bulk_pts) {
            int   c  = s_pidx[3 * p + 0];
            float yf = (float)s_pidx[3 * p + 1];
            float xf = (float)s_pidx[3 * p + 2];
            float dd = s_depth[p];
            float xd = xf * dd;
            float yd = yf * dd;
            float4 r0 = s_cam[c * 3 + 0];
            float4 r1 = s_cam[c * 3 + 1];
            float4 r2 = s_cam[c * 3 + 2];
            float4 o;
            o.x = fmaf(r0.x, xd, fmaf(r0.y, yd, fmaf(r0.z, dd, r0.w)));
            o.y = fmaf(r1.x, xd, fmaf(r1.y, yd, fmaf(r1.z, dd, r1.w)));
            o.z = fmaf(r2.x, xd, fmaf(r2.y, yd, fmaf(r2.z, dd, r2.w)));
            o.w = 1.0f;
            s_out[p] = o;
        }
    }
    __syncthreads();               // s_out complete

    if (tid == 0 && bulk_pts > 0) {
        asm volatile("fence.proxy.async.shared::cta;" ::: "memory");
        bulk_store_s2g(out + (size_t)base * 4, so_addr, (uint32_t)bulk_pts * 16u);
        asm volatile("cp.async.bulk.commit_group;" ::: "memory");
        asm volatile("cp.async.bulk.wait_group 0;" ::: "memory");
    }

    // Scalar remainder (tile_pts % 4) — direct global path (not hit for N=2M).
    for (int p = base + bulk_pts + tid; p < base + tile_pts; p += NTHREADS) {
        int   c  = pidx[3 * p + 0];
        float yf = (float)pidx[3 * p + 1];
        float xf = (float)pidx[3 * p + 2];
        float dd = depth[p];
        float xd = xf * dd;
        float yd = yf * dd;
        float4 r0 = s_cam[c * 3 + 0];
        float4 r1 = s_cam[c * 3 + 1];
        float4 r2 = s_cam[c * 3 + 2];
        float4 o;
        o.x = fmaf(r0.x, xd, fmaf(r0.y, yd, fmaf(r0.z, dd, r0.w)));
        o.y = fmaf(r1.x, xd, fmaf(r1.y, yd, fmaf(r1.z, dd, r1.w)));
        o.z = fmaf(r2.x, xd, fmaf(r2.y, yd, fmaf(r2.z, dd, r2.w)));
        o.w = 1.0f;
        ((float4*)out)[p] = o;
    }
}

extern "C" void kernel_launch(void* const* d_in, const int* in_sizes, int n_in,
                              void* d_out, int out_size) {
    // metadata order: point_indices[N,3] i32, depth[N,1] f32, image_coords (unused),
    //                 camera_to_worlds[C,3,4] f32, intrinsics[C,3,3] f32
    const int*   pidx  = (const int*)d_in[0];
    const float* depth = (const float*)d_in[1];
    const float* c2w   = (const float*)d_in[3];
    const float* intr  = (const float*)d_in[4];
    float*       out   = (float*)d_out;

    int npoints  = in_sizes[0] / 3;
    int num_cams = in_sizes[3] / 12;
    if (num_cams > MAX_CAMS) num_cams = MAX_CAMS;

    int blocks = (npoints + TILE - 1) / TILE;
    point_gen_kernel<<<blocks, NTHREADS>>>(pidx, depth, c2w, intr, out,
                                           npoints, num_cams);
}

// round 6
// speedup vs baseline: 1.5951x; 1.2108x over previous
#include <cuda_runtime.h>
#include <cuda_bf16.h>
#include <cstdint>

// ---------------------------------------------------------------------------
// PointGenerator: X_world = M_c @ [x*d, y*d, d, 1],  M = E_ @ n2r @ K_^-1 (3x4)
//   M[i] = { e_i0/f, -e_i1/f, -M[i].x*cx - M[i].y*cy - e_i2, e_i3 } ; w == 1
//
// R5: TMA input tiles + smem camera table + DIRECT STG.128 output.
// Camera build vectorized (float4). 28KB smem -> 8 blocks/SM.
// ---------------------------------------------------------------------------

#define MAX_CAMS 256
#define NTHREADS 256
#define TILE     1024   // points per block

__device__ __forceinline__ uint32_t smem_u32(const void* p) {
    uint32_t a;
    asm("{ .reg .u64 t; cvta.to.shared.u64 t, %1; cvt.u32.u64 %0, t; }"
        : "=r"(a) : "l"(p));
    return a;
}
__device__ __forceinline__ void mbar_init(uint32_t mbar, uint32_t cnt) {
    asm volatile("mbarrier.init.shared.b64 [%0], %1;" :: "r"(mbar), "r"(cnt) : "memory");
}
__device__ __forceinline__ void mbar_expect_tx(uint32_t mbar, uint32_t bytes) {
    asm volatile("mbarrier.arrive.expect_tx.shared.b64 _, [%0], %1;"
                 :: "r"(mbar), "r"(bytes) : "memory");
}
__device__ __forceinline__ void mbar_wait(uint32_t mbar, uint32_t parity) {
    uint32_t done;
    asm volatile(
        "{ .reg .pred p;\n"
        "  mbarrier.try_wait.parity.acquire.cta.shared::cta.b64 p, [%1], %2;\n"
        "  selp.b32 %0, 1, 0, p; }"
        : "=r"(done) : "r"(mbar), "r"(parity) : "memory");
    if (!done) {
        asm volatile(
            "{ .reg .pred P1;\n"
            "WAIT_%=:\n"
            "  mbarrier.try_wait.parity.acquire.cta.shared::cta.b64 P1, [%0], %1, 0x989680;\n"
            "  @P1 bra.uni DONE_%=;\n"
            "  bra.uni WAIT_%=;\n"
            "DONE_%=: }"
            :: "r"(mbar), "r"(parity) : "memory");
    }
}
__device__ __forceinline__ void bulk_load_g2s(uint32_t smem_dst, const void* gmem_src,
                                              uint32_t bytes, uint32_t mbar) {
    asm volatile(
        "cp.async.bulk.shared::cta.global.mbarrier::complete_tx::bytes [%0], [%1], %2, [%3];"
        :: "r"(smem_dst), "l"(gmem_src), "r"(bytes), "r"(mbar) : "memory");
}

__global__ void __launch_bounds__(NTHREADS)
point_gen_kernel(const int*   __restrict__ pidx,   // [N,3] i32
                 const float* __restrict__ depth,  // [N]   f32
                 const float* __restrict__ c2w,    // [C,3,4] f32
                 const float* __restrict__ intr,   // [C,3,3] f32
                 float*       __restrict__ out,    // [N,4] f32
                 int npoints, int num_cams) {
    __shared__ alignas(128) float4 s_cam[MAX_CAMS * 3];  // 12 KB
    __shared__ alignas(128) int    s_pidx[TILE * 3];     // 12 KB
    __shared__ alignas(128) float  s_depth[TILE];        //  4 KB
    __shared__ alignas(8) unsigned long long s_mbar;

    const int tid  = threadIdx.x;
    const int base = blockIdx.x * TILE;
    int tile_pts   = npoints - base;
    if (tile_pts > TILE) tile_pts = TILE;
    const int bulk_pts = tile_pts & ~3;   // keeps bulk sizes %16 == 0

    const uint32_t mbar    = smem_u32(&s_mbar);
    const uint32_t sp_addr = smem_u32(s_pidx);
    const uint32_t sd_addr = smem_u32(s_depth);

    if (tid == 0) mbar_init(mbar, 1);
    __syncthreads();

    // Kick input TMA first; camera build overlaps its latency.
    if (tid == 0 && bulk_pts > 0) {
        uint32_t b_pidx  = (uint32_t)bulk_pts * 12u;
        uint32_t b_depth = (uint32_t)bulk_pts * 4u;
        mbar_expect_tx(mbar, b_pidx + b_depth);
        bulk_load_g2s(sp_addr, pidx + (size_t)base * 3, b_pidx, mbar);
        bulk_load_g2s(sd_addr, depth + base, b_depth, mbar);
    }

    // Per-camera matrices, vectorized: 3x LDG.128 (E rows) + 3 scalar (f,cx,cy).
    const float4* c2w4 = (const float4*)c2w;   // [C*3] float4 rows
    for (int c = tid; c < num_cams; c += NTHREADS) {
        float f  = __ldg(intr + c * 9 + 0);
        float cx = __ldg(intr + c * 9 + 2);
        float cy = __ldg(intr + c * 9 + 5);
        float invf = 1.0f / f;
#pragma unroll
        for (int i = 0; i < 3; i++) {
            float4 e = c2w4[c * 3 + i];        // {e0, e1, e2, t}
            float4 r;
            r.x = e.x * invf;
            r.y = -e.y * invf;
            r.z = fmaf(-r.x, cx, fmaf(-r.y, cy, -e.z));
            r.w = e.w;
            s_cam[c * 3 + i] = r;
        }
    }
    __syncthreads();                 // cameras visible block-wide
    if (bulk_pts > 0) mbar_wait(mbar, 0);

    float4* out4 = (float4*)out;

    // 4 points per thread; p = tid + j*256 -> coalesced STG.128.
#pragma unroll
    for (int j = 0; j < 4; j++) {
        int p = tid + j * NTHREADS;
        if (p < bulk_pts) {
            int   c  = s_pidx[3 * p + 0];      // stride-3 scalar LDS: conflict-free
            float yf = (float)s_pidx[3 * p + 1];
            float xf = (float)s_pidx[3 * p + 2];
            float dd = s_depth[p];
            float xd = xf * dd;
            float yd = yf * dd;
            float4 r0 = s_cam[c * 3 + 0];
            float4 r1 = s_cam[c * 3 + 1];
            float4 r2 = s_cam[c * 3 + 2];
            float4 o;
            o.x = fmaf(r0.x, xd, fmaf(r0.y, yd, fmaf(r0.z, dd, r0.w)));
            o.y = fmaf(r1.x, xd, fmaf(r1.y, yd, fmaf(r1.z, dd, r1.w)));
            o.z = fmaf(r2.x, xd, fmaf(r2.y, yd, fmaf(r2.z, dd, r2.w)));
            o.w = 1.0f;
            out4[base + p] = o;                // direct STG.128, coalesced
        }
    }

    // Scalar remainder (tile_pts % 4 != 0; never hit for N=2M).
    for (int p = base + bulk_pts + tid; p < base + tile_pts; p += NTHREADS) {
        int   c  = pidx[3 * p + 0];
        float yf = (float)pidx[3 * p + 1];
        float xf = (float)pidx[3 * p + 2];
        float dd = depth[p];
        float xd = xf * dd;
        float yd = yf * dd;
        float4 r0 = s_cam[c * 3 + 0];
        float4 r1 = s_cam[c * 3 + 1];
        float4 r2 = s_cam[c * 3 + 2];
        float4 o;
        o.x = fmaf(r0.x, xd, fmaf(r0.y, yd, fmaf(r0.z, dd, r0.w)));
        o.y = fmaf(r1.x, xd, fmaf(r1.y, yd, fmaf(r1.z, dd, r1.w)));
        o.z = fmaf(r2.x, xd, fmaf(r2.y, yd, fmaf(r2.z, dd, r2.w)));
        o.w = 1.0f;
        out4[p] = o;
    }
}

extern "C" void kernel_launch(void* const* d_in, const int* in_sizes, int n_in,
                              void* d_out, int out_size) {
    // metadata order: point_indices[N,3] i32, depth[N,1] f32, image_coords (unused),
    //                 camera_to_worlds[C,3,4] f32, intrinsics[C,3,3] f32
    const int*   pidx  = (const int*)d_in[0];
    const float* depth = (const float*)d_in[1];
    const float* c2w   = (const float*)d_in[3];
    const float* intr  = (const float*)d_in[4];
    float*       out   = (float*)d_out;

    int npoints  = in_sizes[0] / 3;
    int num_cams = in_sizes[3] / 12;
    if (num_cams > MAX_CAMS) num_cams = MAX_CAMS;

    int blocks = (npoints + TILE - 1) / TILE;
    point_gen_kernel<<<blocks, NTHREADS>>>(pidx, depth, c2w, intr, out,
                                           npoints, num_cams);
}

// round 8
// speedup vs baseline: 1.5981x; 1.0019x over previous
#include <cuda_runtime.h>
#include <cuda_bf16.h>
#include <cstdint>

// ---------------------------------------------------------------------------
// PointGenerator: X_world = M_c @ [x*d, y*d, d, 1],  M = E_ @ n2r @ K_^-1 (3x4)
//   M[i] = { e_i0/f, -e_i1/f, -M[i].x*cx - M[i].y*cy - e_i2, e_i3 } ; w == 1
//
// R6: TILE 2048 (half the block prologues), 8 pts/thread, reg budget ~51,
// branch-free fast path with 2-point batched LDS for latency overlap.
// ---------------------------------------------------------------------------

#define MAX_CAMS 256
#define NTHREADS 256
#define TILE     2048   // points per block
#define PPT      8      // points per thread

__device__ __forceinline__ uint32_t smem_u32(const void* p) {
    uint32_t a;
    asm("{ .reg .u64 t; cvta.to.shared.u64 t, %1; cvt.u32.u64 %0, t; }"
        : "=r"(a) : "l"(p));
    return a;
}
__device__ __forceinline__ void mbar_init(uint32_t mbar, uint32_t cnt) {
    asm volatile("mbarrier.init.shared.b64 [%0], %1;" :: "r"(mbar), "r"(cnt) : "memory");
}
__device__ __forceinline__ void mbar_expect_tx(uint32_t mbar, uint32_t bytes) {
    asm volatile("mbarrier.arrive.expect_tx.shared.b64 _, [%0], %1;"
                 :: "r"(mbar), "r"(bytes) : "memory");
}
__device__ __forceinline__ void mbar_wait(uint32_t mbar, uint32_t parity) {
    uint32_t done;
    asm volatile(
        "{ .reg .pred p;\n"
        "  mbarrier.try_wait.parity.acquire.cta.shared::cta.b64 p, [%1], %2;\n"
        "  selp.b32 %0, 1, 0, p; }"
        : "=r"(done) : "r"(mbar), "r"(parity) : "memory");
    if (!done) {
        asm volatile(
            "{ .reg .pred P1;\n"
            "WAIT_%=:\n"
            "  mbarrier.try_wait.parity.acquire.cta.shared::cta.b64 P1, [%0], %1, 0x989680;\n"
            "  @P1 bra.uni DONE_%=;\n"
            "  bra.uni WAIT_%=;\n"
            "DONE_%=: }"
            :: "r"(mbar), "r"(parity) : "memory");
    }
}
__device__ __forceinline__ void bulk_load_g2s(uint32_t smem_dst, const void* gmem_src,
                                              uint32_t bytes, uint32_t mbar) {
    asm volatile(
        "cp.async.bulk.shared::cta.global.mbarrier::complete_tx::bytes [%0], [%1], %2, [%3];"
        :: "r"(smem_dst), "l"(gmem_src), "r"(bytes), "r"(mbar) : "memory");
}

struct SmemLayout {
    float4 cam[MAX_CAMS * 3];                 // 12 KB
    int    pidx[TILE * 3];                    // 24 KB
    float  depth[TILE];                       //  8 KB
    alignas(8) unsigned long long mbar;
};

__device__ __forceinline__ float4 transform(const float4* __restrict__ s_cam,
                                            int c, float xf, float yf, float dd) {
    float xd = xf * dd;
    float yd = yf * dd;
    float4 r0 = s_cam[c * 3 + 0];
    float4 r1 = s_cam[c * 3 + 1];
    float4 r2 = s_cam[c * 3 + 2];
    float4 o;
    o.x = fmaf(r0.x, xd, fmaf(r0.y, yd, fmaf(r0.z, dd, r0.w)));
    o.y = fmaf(r1.x, xd, fmaf(r1.y, yd, fmaf(r1.z, dd, r1.w)));
    o.z = fmaf(r2.x, xd, fmaf(r2.y, yd, fmaf(r2.z, dd, r2.w)));
    o.w = 1.0f;
    return o;
}

__global__ void __launch_bounds__(NTHREADS, 5)
point_gen_kernel(const int*   __restrict__ pidx,   // [N,3] i32
                 const float* __restrict__ depth,  // [N]   f32
                 const float* __restrict__ c2w,    // [C,3,4] f32
                 const float* __restrict__ intr,   // [C,3,3] f32
                 float*       __restrict__ out,    // [N,4] f32
                 int npoints, int num_cams) {
    __shared__ SmemLayout sm;

    const int tid  = threadIdx.x;
    const int base = blockIdx.x * TILE;
    int tile_pts   = npoints - base;
    if (tile_pts > TILE) tile_pts = TILE;
    const int bulk_pts = tile_pts & ~3;   // TMA sizes stay %16 == 0

    const uint32_t mbar    = smem_u32(&sm.mbar);
    const uint32_t sp_addr = smem_u32(sm.pidx);
    const uint32_t sd_addr = smem_u32(sm.depth);

    if (tid == 0) mbar_init(mbar, 1);
    __syncthreads();

    if (tid == 0 && bulk_pts > 0) {
        uint32_t b_pidx  = (uint32_t)bulk_pts * 12u;
        uint32_t b_depth = (uint32_t)bulk_pts * 4u;
        mbar_expect_tx(mbar, b_pidx + b_depth);
        bulk_load_g2s(sp_addr, pidx + (size_t)base * 3, b_pidx, mbar);
        bulk_load_g2s(sd_addr, depth + base, b_depth, mbar);
    }

    // Camera matrices: 3x LDG.128 + 3 scalar LDG per camera, overlaps the TMA.
    const float4* c2w4 = (const float4*)c2w;
    for (int c = tid; c < num_cams; c += NTHREADS) {
        float f  = __ldg(intr + c * 9 + 0);
        float cx = __ldg(intr + c * 9 + 2);
        float cy = __ldg(intr + c * 9 + 5);
        float invf = 1.0f / f;
#pragma unroll
        for (int i = 0; i < 3; i++) {
            float4 e = c2w4[c * 3 + i];        // {e0, e1, e2, t}
            float4 r;
            r.x = e.x * invf;
            r.y = -e.y * invf;
            r.z = fmaf(-r.x, cx, fmaf(-r.y, cy, -e.z));
            r.w = e.w;
            sm.cam[c * 3 + i] = r;
        }
    }
    __syncthreads();
    if (bulk_pts > 0) mbar_wait(mbar, 0);

    float4* out4 = (float4*)out;

    if (tile_pts == TILE) {
        // ---- fast path: branch-free, 2-point batched loads ----
#pragma unroll
        for (int j = 0; j < PPT; j += 2) {
            int p0 = tid + (j + 0) * NTHREADS;
            int p1 = tid + (j + 1) * NTHREADS;
            // batch all scalar index/depth loads
            int   c0 = sm.pidx[3 * p0 + 0];
            int   c1 = sm.pidx[3 * p1 + 0];
            float y0 = (float)sm.pidx[3 * p0 + 1];
            float y1 = (float)sm.pidx[3 * p1 + 1];
            float x0 = (float)sm.pidx[3 * p0 + 2];
            float x1 = (float)sm.pidx[3 * p1 + 2];
            float d0 = sm.depth[p0];
            float d1 = sm.depth[p1];
            float4 o0 = transform(sm.cam, c0, x0, y0, d0);
            float4 o1 = transform(sm.cam, c1, x1, y1, d1);
            out4[base + p0] = o0;
            out4[base + p1] = o1;
        }
    } else {
        // ---- edge tile: predicated ----
#pragma unroll
        for (int j = 0; j < PPT; j++) {
            int p = tid + j * NTHREADS;
            if (p < bulk_pts) {
                int   c  = sm.pidx[3 * p + 0];
                float yf = (float)sm.pidx[3 * p + 1];
                float xf = (float)sm.pidx[3 * p + 2];
                float dd = sm.depth[p];
                out4[base + p] = transform(sm.cam, c, xf, yf, dd);
            }
        }
        // scalar remainder (tile_pts % 4 != 0; never hit for N=2M)
        for (int p = base + bulk_pts + tid; p < base + tile_pts; p += NTHREADS) {
            int   c  = pidx[3 * p + 0];
            float yf = (float)pidx[3 * p + 1];
            float xf = (float)pidx[3 * p + 2];
            float dd = depth[p];
            out4[p] = transform(sm.cam, c, xf, yf, dd);
        }
    }
}

extern "C" void kernel_launch(void* const* d_in, const int* in_sizes, int n_in,
                              void* d_out, int out_size) {
    // metadata order: point_indices[N,3] i32, depth[N,1] f32, image_coords (unused),
    //                 camera_to_worlds[C,3,4] f32, intrinsics[C,3,3] f32
    const int*   pidx  = (const int*)d_in[0];
    const float* depth = (const float*)d_in[1];
    const float* c2w   = (const float*)d_in[3];
    const float* intr  = (const float*)d_in[4];
    float*       out   = (float*)d_out;

    int npoints  = in_sizes[0] / 3;
    int num_cams = in_sizes[3] / 12;
    if (num_cams > MAX_CAMS) num_cams = MAX_CAMS;

    int blocks = (npoints + TILE - 1) / TILE;
    point_gen_kernel<<<blocks, NTHREADS>>>(pidx, depth, c2w, intr, out,
                                           npoints, num_cams);
}